// round 1
// baseline (speedup 1.0000x reference)
#include <cuda_runtime.h>
#include <math.h>

#define DIM 1536
#define NH 12
#define HD 128
#define SMAX 4800

// ---------------- scratch (no cudaMalloc allowed) ----------------
__device__ float g_bufq[SMAX * DIM];   // q: pre-GEMM -> rms -> rope (in place)
__device__ float g_bufk[SMAX * DIM];
__device__ float g_bufv[SMAX * DIM];
__device__ float g_bufxl[SMAX * DIM];  // x_local then += gating
__device__ float g_zbuf[SMAX * NH];
__device__ float g_Gmat[NH * HD * HD]; // G[n][d][j] = sum_m g_kv[n][d][m] * Wlin[j][m]

// ---------------- generic NT GEMM: C[M,N] = A[M,K] @ B[N,K]^T + bias ----------------
__device__ __forceinline__ void gemm_body(
    const float* __restrict__ A, const float* __restrict__ B,
    const float* __restrict__ bias, float* __restrict__ C,
    int M, int N, int K)
{
    __shared__ float As[16][128];
    __shared__ float Bs[16][128];
    const int bm = blockIdx.y * 128;
    const int bn = blockIdx.x * 128;
    const int tid = threadIdx.x;
    const int lr = tid >> 2;          // 0..63
    const int lc = (tid & 3) << 2;    // 0,4,8,12
    const int tr = (tid >> 4) << 3;   // 0..120
    const int tc = (tid & 15) << 3;   // 0..120

    float acc[8][8];
#pragma unroll
    for (int i = 0; i < 8; i++)
#pragma unroll
        for (int j = 0; j < 8; j++) acc[i][j] = 0.f;

    for (int k0 = 0; k0 < K; k0 += 16) {
#pragma unroll
        for (int ph = 0; ph < 2; ph++) {
            int ar = bm + lr + ph * 64;
            float4 va = make_float4(0.f, 0.f, 0.f, 0.f);
            if (ar < M) va = *(const float4*)(A + (size_t)ar * K + k0 + lc);
            As[lc + 0][lr + ph * 64] = va.x;
            As[lc + 1][lr + ph * 64] = va.y;
            As[lc + 2][lr + ph * 64] = va.z;
            As[lc + 3][lr + ph * 64] = va.w;
            int br = bn + lr + ph * 64;   // N is a multiple of 128 -> always valid
            float4 vb = *(const float4*)(B + (size_t)br * K + k0 + lc);
            Bs[lc + 0][lr + ph * 64] = vb.x;
            Bs[lc + 1][lr + ph * 64] = vb.y;
            Bs[lc + 2][lr + ph * 64] = vb.z;
            Bs[lc + 3][lr + ph * 64] = vb.w;
        }
        __syncthreads();
#pragma unroll
        for (int kk = 0; kk < 16; kk++) {
            float4 a0 = *(const float4*)&As[kk][tr];
            float4 a1 = *(const float4*)&As[kk][tr + 4];
            float4 b0 = *(const float4*)&Bs[kk][tc];
            float4 b1 = *(const float4*)&Bs[kk][tc + 4];
            float a[8] = {a0.x, a0.y, a0.z, a0.w, a1.x, a1.y, a1.z, a1.w};
            float b[8] = {b0.x, b0.y, b0.z, b0.w, b1.x, b1.y, b1.z, b1.w};
#pragma unroll
            for (int i = 0; i < 8; i++)
#pragma unroll
                for (int j = 0; j < 8; j++) acc[i][j] += a[i] * b[j];
        }
        __syncthreads();
    }
#pragma unroll
    for (int i = 0; i < 8; i++) {
        int row = bm + tr + i;
        if (row < M) {
            float* cp = C + (size_t)row * N + bn + tc;
            const float* bp = bias + bn + tc;
#pragma unroll
            for (int j = 0; j < 8; j++) cp[j] = acc[i][j] + bp[j];
        }
    }
}

__global__ void __launch_bounds__(256) gemm_nt_bias(
    const float* __restrict__ A, const float* __restrict__ B,
    const float* __restrict__ bias, float* __restrict__ C,
    int M, int N, int K)
{
    gemm_body(A, B, bias, C, M, N, K);
}

// fused q/k/v projections: blockIdx.z picks which weight/out
__global__ void __launch_bounds__(256) gemm_qkv(
    const float* __restrict__ X,
    const float* __restrict__ Wq, const float* __restrict__ bq,
    const float* __restrict__ Wk, const float* __restrict__ bk,
    const float* __restrict__ Wv, const float* __restrict__ bv,
    float* __restrict__ outq, float* __restrict__ outk, float* __restrict__ outv,
    int M)
{
    const float* W; const float* b; float* O;
    if (blockIdx.z == 0)      { W = Wq; b = bq; O = outq; }
    else if (blockIdx.z == 1) { W = Wk; b = bk; O = outk; }
    else                      { W = Wv; b = bv; O = outv; }
    gemm_body(X, W, b, O, M, DIM, DIM);
}

// ---------------- RMS norm (in place), row of DIM ----------------
__global__ void __launch_bounds__(256) rms_kernel(
    float* __restrict__ q, float* __restrict__ k,
    const float* __restrict__ gq, const float* __restrict__ gk, int S)
{
    int s = blockIdx.x;
    float* row = (blockIdx.y == 0 ? q : k) + (size_t)s * DIM;
    const float* g = (blockIdx.y == 0 ? gq : gk);
    int tid = threadIdx.x;

    float ss = 0.f;
    for (int i = tid * 4; i < DIM; i += 1024) {
        float4 v = *(const float4*)(row + i);
        ss += v.x * v.x + v.y * v.y + v.z * v.z + v.w * v.w;
    }
#pragma unroll
    for (int o = 16; o; o >>= 1) ss += __shfl_xor_sync(0xffffffffu, ss, o);
    __shared__ float ps[8];
    __shared__ float scl;
    if ((tid & 31) == 0) ps[tid >> 5] = ss;
    __syncthreads();
    if (tid == 0) {
        float t = 0.f;
#pragma unroll
        for (int i = 0; i < 8; i++) t += ps[i];
        scl = rsqrtf(t * (1.0f / DIM) + 1e-6f);
    }
    __syncthreads();
    float sc = scl;
    for (int i = tid * 4; i < DIM; i += 1024) {
        float4 v = *(const float4*)(row + i);
        float4 gv = *(const float4*)(g + i);
        v.x *= sc * gv.x; v.y *= sc * gv.y; v.z *= sc * gv.z; v.w *= sc * gv.w;
        *(float4*)(row + i) = v;
    }
}

// ---------------- z = 1/(relu(q) . g_kmean + 1e-6), one warp per (s,n) ----------------
__global__ void __launch_bounds__(256) z_kernel(
    const float* __restrict__ q, const float* __restrict__ gkm,
    float* __restrict__ z, int SN)
{
    int idx = blockIdx.x * 8 + (threadIdx.x >> 5);
    if (idx >= SN) return;
    int lane = threadIdx.x & 31;
    int s = idx / NH;
    int n = idx - s * NH;
    const float* qr = q + (size_t)s * DIM + n * HD;
    const float* gm = gkm + n * HD;
    float acc = 0.f;
#pragma unroll
    for (int d = lane; d < HD; d += 32) acc += fmaxf(qr[d], 0.f) * gm[d];
#pragma unroll
    for (int o = 16; o; o >>= 1) acc += __shfl_xor_sync(0xffffffffu, acc, o);
    if (lane == 0) z[idx] = 1.f / (acc + 1e-6f);
}

// ---------------- RoPE in place (c=64 pairs: [0,22) frame, [22,43) h, [43,64) w) -------
__global__ void rope_kernel(
    float* __restrict__ q, float* __restrict__ k,
    const float* __restrict__ freqs,
    const int* __restrict__ ph, const int* __restrict__ pw, int S)
{
    int s = blockIdx.x;
    int n = blockIdx.y;
    float* buf = (blockIdx.z == 0 ? q : k) + (size_t)s * DIM + n * HD;
    int hg = *ph;
    int wg = *pw;
    int hw = hg * wg;
    int f = s / hw;
    int rem = s - f * hw;
    int hh = rem / wg;
    int ww = rem - hh * wg;
    int j = threadIdx.x;                 // pair index 0..63
    int pos = (j < 22) ? f : ((j < 43) ? hh : ww);
    float cr = freqs[(pos * 64 + j) * 2 + 0];
    float ci = freqs[(pos * 64 + j) * 2 + 1];
    float xr = buf[2 * j];
    float xi = buf[2 * j + 1];
    buf[2 * j]     = xr * cr - xi * ci;
    buf[2 * j + 1] = xr * ci + xi * cr;
}

// ---------------- G[n][d][j] = sum_m g_kv[n][d][m] * Wlin[j][m] ----------------
__global__ void __launch_bounds__(256) gmat_kernel(
    const float* __restrict__ gkv, const float* __restrict__ Wlin,
    float* __restrict__ G)
{
    int n = blockIdx.x;
    int jb = blockIdx.y * 64;
    __shared__ float Wl[64][128];
    int tid = threadIdx.x;
    for (int i = tid; i < 64 * 128; i += 256)
        Wl[i >> 7][i & 127] = Wlin[(jb + (i >> 7)) * HD + (i & 127)];
    __syncthreads();
    for (int o = tid; o < 128 * 64; o += 256) {
        int d = o >> 6;
        int jl = o & 63;
        const float* gr = gkv + ((size_t)n * HD + d) * HD;
        float acc = 0.f;
#pragma unroll 8
        for (int m = 0; m < HD; m++) acc += gr[m] * Wl[jl][m];
        G[((size_t)n * HD + d) * HD + jb + jl] = acc;
    }
}

// ---------------- fp32 flash attention, 64(q) x 64(k) tiles ----------------
__global__ void __launch_bounds__(256) attn_kernel(
    const float* __restrict__ rq, const float* __restrict__ rk,
    const float* __restrict__ v, float* __restrict__ xl, int S)
{
    extern __shared__ float sm[];
    float* Qs = sm;                 // 64*128
    float* Ks = Qs + 64 * 128;      // 64*128
    float* Vs = Ks + 64 * 128;      // 64*128
    float* Ss = Vs + 64 * 128;      // 64*65 (pad avoids row-broadcast bank conflict)
    float* rmx = Ss + 64 * 65;      // 64
    float* rls = rmx + 64;          // 64
    float* ral = rls + 64;          // 64

    const int n = blockIdx.y;
    const int q0 = blockIdx.x * 64;
    const int tid = threadIdx.x;
    const float scale = 0.08838834764831843f; // 128^-0.5

    // load Q tile
    for (int i = tid; i < 64 * 32; i += 256) {
        int r = i >> 5, c = (i & 31) << 2;
        int s = q0 + r;
        float4 val = make_float4(0.f, 0.f, 0.f, 0.f);
        if (s < S) val = *(const float4*)(rq + (size_t)s * DIM + n * HD + c);
        *(float4*)(Qs + r * 128 + c) = val;
    }
    if (tid < 64) { rmx[tid] = -1e30f; rls[tid] = 0.f; }

    const int trs = (tid >> 4) << 2;   // row base (scores and O)
    const int tcs = (tid & 15) << 2;   // score col base
    const int tco = (tid & 15) << 3;   // O col base (d)
    float acc[4][8];
#pragma unroll
    for (int i = 0; i < 4; i++)
#pragma unroll
        for (int j = 0; j < 8; j++) acc[i][j] = 0.f;
    __syncthreads();

    const int nkt = (S + 63) >> 6;
    for (int kt = 0; kt < nkt; kt++) {
        int k0 = kt * 64;
        // load K,V tiles
        for (int i = tid; i < 64 * 32; i += 256) {
            int r = i >> 5, c = (i & 31) << 2;
            int t = k0 + r;
            float4 kvk = make_float4(0.f, 0.f, 0.f, 0.f);
            float4 kvv = make_float4(0.f, 0.f, 0.f, 0.f);
            if (t < S) {
                kvk = *(const float4*)(rk + (size_t)t * DIM + n * HD + c);
                kvv = *(const float4*)(v  + (size_t)t * DIM + n * HD + c);
            }
            *(float4*)(Ks + r * 128 + c) = kvk;
            *(float4*)(Vs + r * 128 + c) = kvv;
        }
        __syncthreads();

        // scores: 4x4 per thread
        float sacc[4][4];
#pragma unroll
        for (int i = 0; i < 4; i++)
#pragma unroll
            for (int j = 0; j < 4; j++) sacc[i][j] = 0.f;
#pragma unroll 8
        for (int d = 0; d < 128; d += 4) {
            float4 qv[4], kv[4];
#pragma unroll
            for (int i = 0; i < 4; i++) qv[i] = *(const float4*)(Qs + (trs + i) * 128 + d);
#pragma unroll
            for (int j = 0; j < 4; j++) kv[j] = *(const float4*)(Ks + (tcs + j) * 128 + d);
#pragma unroll
            for (int i = 0; i < 4; i++)
#pragma unroll
                for (int j = 0; j < 4; j++)
                    sacc[i][j] += qv[i].x * kv[j].x + qv[i].y * kv[j].y +
                                  qv[i].z * kv[j].z + qv[i].w * kv[j].w;
        }
#pragma unroll
        for (int i = 0; i < 4; i++)
#pragma unroll
            for (int j = 0; j < 4; j++) {
                float val = sacc[i][j] * scale;
                if (k0 + tcs + j >= S) val = -1e30f;
                Ss[(trs + i) * 65 + tcs + j] = val;
            }
        __syncthreads();

        // per-row online softmax (threads 0..63, one row each)
        if (tid < 64) {
            float mold = rmx[tid];
            float mx = mold;
            float* srow = Ss + tid * 65;
#pragma unroll 8
            for (int c = 0; c < 64; c++) mx = fmaxf(mx, srow[c]);
            float a = __expf(mold - mx);
            float sum = 0.f;
#pragma unroll 8
            for (int c = 0; c < 64; c++) {
                float p = __expf(srow[c] - mx);
                srow[c] = p;
                sum += p;
            }
            rls[tid] = rls[tid] * a + sum;
            rmx[tid] = mx;
            ral[tid] = a;
        }
        __syncthreads();

        // rescale + PV
        float al[4];
#pragma unroll
        for (int i = 0; i < 4; i++) al[i] = ral[trs + i];
#pragma unroll
        for (int i = 0; i < 4; i++)
#pragma unroll
            for (int j = 0; j < 8; j++) acc[i][j] *= al[i];
#pragma unroll 4
        for (int c = 0; c < 64; c++) {
            float p0 = Ss[(trs + 0) * 65 + c];
            float p1 = Ss[(trs + 1) * 65 + c];
            float p2 = Ss[(trs + 2) * 65 + c];
            float p3 = Ss[(trs + 3) * 65 + c];
            float4 v0 = *(const float4*)(Vs + c * 128 + tco);
            float4 v1 = *(const float4*)(Vs + c * 128 + tco + 4);
            acc[0][0] += p0 * v0.x; acc[0][1] += p0 * v0.y; acc[0][2] += p0 * v0.z; acc[0][3] += p0 * v0.w;
            acc[0][4] += p0 * v1.x; acc[0][5] += p0 * v1.y; acc[0][6] += p0 * v1.z; acc[0][7] += p0 * v1.w;
            acc[1][0] += p1 * v0.x; acc[1][1] += p1 * v0.y; acc[1][2] += p1 * v0.z; acc[1][3] += p1 * v0.w;
            acc[1][4] += p1 * v1.x; acc[1][5] += p1 * v1.y; acc[1][6] += p1 * v1.z; acc[1][7] += p1 * v1.w;
            acc[2][0] += p2 * v0.x; acc[2][1] += p2 * v0.y; acc[2][2] += p2 * v0.z; acc[2][3] += p2 * v0.w;
            acc[2][4] += p2 * v1.x; acc[2][5] += p2 * v1.y; acc[2][6] += p2 * v1.z; acc[2][7] += p2 * v1.w;
            acc[3][0] += p3 * v0.x; acc[3][1] += p3 * v0.y; acc[3][2] += p3 * v0.z; acc[3][3] += p3 * v0.w;
            acc[3][4] += p3 * v1.x; acc[3][5] += p3 * v1.y; acc[3][6] += p3 * v1.z; acc[3][7] += p3 * v1.w;
        }
        __syncthreads();
    }

    float il[4];
#pragma unroll
    for (int i = 0; i < 4; i++) il[i] = 1.f / rls[trs + i];
#pragma unroll
    for (int i = 0; i < 4; i++) {
        int s = q0 + trs + i;
        if (s < S) {
            float4 o0 = make_float4(acc[i][0] * il[i], acc[i][1] * il[i],
                                    acc[i][2] * il[i], acc[i][3] * il[i]);
            float4 o1 = make_float4(acc[i][4] * il[i], acc[i][5] * il[i],
                                    acc[i][6] * il[i], acc[i][7] * il[i]);
            *(float4*)(xl + (size_t)s * DIM + n * HD + tco) = o0;
            *(float4*)(xl + (size_t)s * DIM + n * HD + tco + 4) = o1;
        }
    }
}

// ---------------- gating: xl[s, n*128+j] += z[s,n] * (rq . G[n][:][j]) + blin[j] --------
__global__ void __launch_bounds__(256) gate_kernel(
    const float* __restrict__ rq, const float* __restrict__ G,
    const float* __restrict__ z, const float* __restrict__ blin,
    float* __restrict__ xl, int S)
{
    __shared__ float Qs[32][128];
    int n = blockIdx.y;
    int s0 = blockIdx.x * 32;
    int tid = threadIdx.x;
    for (int i = tid; i < 32 * 32; i += 256) {
        int r = i >> 5, c = (i & 31) << 2;
        int s = s0 + r;
        float4 val = make_float4(0.f, 0.f, 0.f, 0.f);
        if (s < S) val = *(const float4*)(rq + (size_t)s * DIM + n * HD + c);
        *(float4*)(&Qs[r][c]) = val;
    }
    __syncthreads();
    int j = tid & 127;
    int half = tid >> 7;   // two 16-row groups
    float acc[16];
#pragma unroll
    for (int r = 0; r < 16; r++) acc[r] = 0.f;
    const float* gp = G + (size_t)n * HD * HD + j;  // stride HD over d, coalesced over j
#pragma unroll 4
    for (int d = 0; d < 128; d++) {
        float gg = gp[d * HD];
#pragma unroll
        for (int r = 0; r < 16; r++) acc[r] += Qs[half * 16 + r][d] * gg;
    }
    float bl = blin[j];
#pragma unroll
    for (int r = 0; r < 16; r++) {
        int s = s0 + half * 16 + r;
        if (s < S) {
            float zz = z[s * NH + n];
            xl[(size_t)s * DIM + n * HD + j] += zz * acc[r] + bl;
        }
    }
}

// ---------------- launch ----------------
extern "C" void kernel_launch(void* const* d_in, const int* in_sizes, int n_in,
                              void* d_out, int out_size)
{
    const float* x    = (const float*)d_in[0];
    const float* freqs= (const float*)d_in[1];
    const float* gkm  = (const float*)d_in[2];
    const float* gkv  = (const float*)d_in[3];
    const float* Wq   = (const float*)d_in[4];
    const float* bq   = (const float*)d_in[5];
    const float* Wk   = (const float*)d_in[6];
    const float* bk   = (const float*)d_in[7];
    const float* Wv   = (const float*)d_in[8];
    const float* bv   = (const float*)d_in[9];
    const float* Wo   = (const float*)d_in[10];
    const float* bo   = (const float*)d_in[11];
    const float* gq   = (const float*)d_in[12];
    const float* gk   = (const float*)d_in[13];
    const float* Wlin = (const float*)d_in[14];
    const float* blin = (const float*)d_in[15];
    const int*   ph   = (const int*)d_in[17];
    const int*   pw   = (const int*)d_in[18];
    float* out = (float*)d_out;

    const int S = in_sizes[0] / DIM;

    float *bufq, *bufk, *bufv, *bufxl, *zb, *Gb;
    cudaGetSymbolAddress((void**)&bufq,  g_bufq);
    cudaGetSymbolAddress((void**)&bufk,  g_bufk);
    cudaGetSymbolAddress((void**)&bufv,  g_bufv);
    cudaGetSymbolAddress((void**)&bufxl, g_bufxl);
    cudaGetSymbolAddress((void**)&zb,    g_zbuf);
    cudaGetSymbolAddress((void**)&Gb,    g_Gmat);

    const int mt = (S + 127) / 128;

    // 1. q/k/v projections (fused launch)
    gemm_qkv<<<dim3(DIM / 128, mt, 3), 256>>>(x, Wq, bq, Wk, bk, Wv, bv,
                                              bufq, bufk, bufv, S);
    // 2. rms norm (in place) on q and k
    rms_kernel<<<dim3(S, 2), 256>>>(bufq, bufk, gq, gk, S);
    // 3. z from post-rms pre-rope q
    z_kernel<<<(S * NH + 7) / 8, 256>>>(bufq, gkm, zb, S * NH);
    // 4. rope in place on q and k
    rope_kernel<<<dim3(S, NH, 2), 64>>>(bufq, bufk, freqs, ph, pw, S);
    // 5. G[n] = g_kv[n] @ Wlin^T
    gmat_kernel<<<dim3(NH, 2), 256>>>(gkv, Wlin, Gb);
    // 6. attention -> bufxl
    const int attn_smem = (3 * 64 * 128 + 64 * 65 + 192) * 4;
    cudaFuncSetAttribute(attn_kernel, cudaFuncAttributeMaxDynamicSharedMemorySize, attn_smem);
    attn_kernel<<<dim3((S + 63) / 64, NH), 256, attn_smem>>>(bufq, bufk, bufv, bufxl, S);
    // 7. gating += into bufxl
    gate_kernel<<<dim3((S + 31) / 32, NH), 256>>>(bufq, Gb, zb, blin, bufxl, S);
    // 8. output projection
    gemm_nt_bias<<<dim3(DIM / 128, mt), 256>>>(bufxl, Wo, bo, out, S, DIM, DIM);
}

// round 2
// speedup vs baseline: 1.4905x; 1.4905x over previous
#include <cuda_runtime.h>
#include <math.h>

#define DIM 1536
#define NH 12
#define HD 128
#define SMAX 4800

// ---------------- scratch (no cudaMalloc allowed) ----------------
__device__ float g_bufq[SMAX * DIM];   // q: pre-GEMM -> rms -> rope (in place)
__device__ float g_bufk[SMAX * DIM];
__device__ float g_bufv[SMAX * DIM];
__device__ float g_bufxl[SMAX * DIM];  // x_local then += gating
__device__ float g_zbuf[SMAX * NH];
__device__ float g_Gmat[NH * HD * HD]; // G[n][d][j] = sum_m g_kv[n][d][m] * Wlin[j][m]

// ---------------- tf32 helpers ----------------
__device__ __forceinline__ float tf32r(float x) {
    unsigned u;
    asm("cvt.rna.tf32.f32 %0, %1;" : "=r"(u) : "f"(x));
    return __uint_as_float(u);
}

__device__ __forceinline__ void mma8(float* c, float a0, float a1, float a2, float a3,
                                     float b0, float b1) {
    asm volatile(
        "mma.sync.aligned.m16n8k8.row.col.f32.tf32.tf32.f32 "
        "{%0,%1,%2,%3}, {%4,%5,%6,%7}, {%8,%9}, {%0,%1,%2,%3};"
        : "+f"(c[0]), "+f"(c[1]), "+f"(c[2]), "+f"(c[3])
        : "r"(__float_as_uint(a0)), "r"(__float_as_uint(a1)),
          "r"(__float_as_uint(a2)), "r"(__float_as_uint(a3)),
          "r"(__float_as_uint(b0)), "r"(__float_as_uint(b1)));
}

// ---------------- generic NT GEMM: C[M,N] = A[M,K] @ B[N,K]^T + bias ----------------
__device__ __forceinline__ void gemm_body(
    const float* __restrict__ A, const float* __restrict__ B,
    const float* __restrict__ bias, float* __restrict__ C,
    int M, int N, int K)
{
    __shared__ float As[16][128];
    __shared__ float Bs[16][128];
    const int bm = blockIdx.y * 128;
    const int bn = blockIdx.x * 128;
    const int tid = threadIdx.x;
    const int lr = tid >> 2;          // 0..63
    const int lc = (tid & 3) << 2;    // 0,4,8,12
    const int tr = (tid >> 4) << 3;   // 0..120
    const int tc = (tid & 15) << 3;   // 0..120

    float acc[8][8];
#pragma unroll
    for (int i = 0; i < 8; i++)
#pragma unroll
        for (int j = 0; j < 8; j++) acc[i][j] = 0.f;

    for (int k0 = 0; k0 < K; k0 += 16) {
#pragma unroll
        for (int ph = 0; ph < 2; ph++) {
            int ar = bm + lr + ph * 64;
            float4 va = make_float4(0.f, 0.f, 0.f, 0.f);
            if (ar < M) va = *(const float4*)(A + (size_t)ar * K + k0 + lc);
            As[lc + 0][lr + ph * 64] = va.x;
            As[lc + 1][lr + ph * 64] = va.y;
            As[lc + 2][lr + ph * 64] = va.z;
            As[lc + 3][lr + ph * 64] = va.w;
            int br = bn + lr + ph * 64;   // N is a multiple of 128 -> always valid
            float4 vb = *(const float4*)(B + (size_t)br * K + k0 + lc);
            Bs[lc + 0][lr + ph * 64] = vb.x;
            Bs[lc + 1][lr + ph * 64] = vb.y;
            Bs[lc + 2][lr + ph * 64] = vb.z;
            Bs[lc + 3][lr + ph * 64] = vb.w;
        }
        __syncthreads();
#pragma unroll
        for (int kk = 0; kk < 16; kk++) {
            float4 a0 = *(const float4*)&As[kk][tr];
            float4 a1 = *(const float4*)&As[kk][tr + 4];
            float4 b0 = *(const float4*)&Bs[kk][tc];
            float4 b1 = *(const float4*)&Bs[kk][tc + 4];
            float a[8] = {a0.x, a0.y, a0.z, a0.w, a1.x, a1.y, a1.z, a1.w};
            float b[8] = {b0.x, b0.y, b0.z, b0.w, b1.x, b1.y, b1.z, b1.w};
#pragma unroll
            for (int i = 0; i < 8; i++)
#pragma unroll
                for (int j = 0; j < 8; j++) acc[i][j] += a[i] * b[j];
        }
        __syncthreads();
    }
#pragma unroll
    for (int i = 0; i < 8; i++) {
        int row = bm + tr + i;
        if (row < M) {
            float* cp = C + (size_t)row * N + bn + tc;
            const float* bp = bias + bn + tc;
#pragma unroll
            for (int j = 0; j < 8; j++) cp[j] = acc[i][j] + bp[j];
        }
    }
}

__global__ void __launch_bounds__(256) gemm_nt_bias(
    const float* __restrict__ A, const float* __restrict__ B,
    const float* __restrict__ bias, float* __restrict__ C,
    int M, int N, int K)
{
    gemm_body(A, B, bias, C, M, N, K);
}

// fused q/k/v projections: blockIdx.z picks which weight/out
__global__ void __launch_bounds__(256) gemm_qkv(
    const float* __restrict__ X,
    const float* __restrict__ Wq, const float* __restrict__ bq,
    const float* __restrict__ Wk, const float* __restrict__ bk,
    const float* __restrict__ Wv, const float* __restrict__ bv,
    float* __restrict__ outq, float* __restrict__ outk, float* __restrict__ outv,
    int M)
{
    const float* W; const float* b; float* O;
    if (blockIdx.z == 0)      { W = Wq; b = bq; O = outq; }
    else if (blockIdx.z == 1) { W = Wk; b = bk; O = outk; }
    else                      { W = Wv; b = bv; O = outv; }
    gemm_body(X, W, b, O, M, DIM, DIM);
}

// ---------------- RMS norm (in place), row of DIM ----------------
__global__ void __launch_bounds__(256) rms_kernel(
    float* __restrict__ q, float* __restrict__ k,
    const float* __restrict__ gq, const float* __restrict__ gk, int S)
{
    int s = blockIdx.x;
    float* row = (blockIdx.y == 0 ? q : k) + (size_t)s * DIM;
    const float* g = (blockIdx.y == 0 ? gq : gk);
    int tid = threadIdx.x;

    float ss = 0.f;
    for (int i = tid * 4; i < DIM; i += 1024) {
        float4 v = *(const float4*)(row + i);
        ss += v.x * v.x + v.y * v.y + v.z * v.z + v.w * v.w;
    }
#pragma unroll
    for (int o = 16; o; o >>= 1) ss += __shfl_xor_sync(0xffffffffu, ss, o);
    __shared__ float ps[8];
    __shared__ float scl;
    if ((tid & 31) == 0) ps[tid >> 5] = ss;
    __syncthreads();
    if (tid == 0) {
        float t = 0.f;
#pragma unroll
        for (int i = 0; i < 8; i++) t += ps[i];
        scl = rsqrtf(t * (1.0f / DIM) + 1e-6f);
    }
    __syncthreads();
    float sc = scl;
    for (int i = tid * 4; i < DIM; i += 1024) {
        float4 v = *(const float4*)(row + i);
        float4 gv = *(const float4*)(g + i);
        v.x *= sc * gv.x; v.y *= sc * gv.y; v.z *= sc * gv.z; v.w *= sc * gv.w;
        *(float4*)(row + i) = v;
    }
}

// ---------------- z = 1/(relu(q) . g_kmean + 1e-6), one warp per (s,n) ----------------
__global__ void __launch_bounds__(256) z_kernel(
    const float* __restrict__ q, const float* __restrict__ gkm,
    float* __restrict__ z, int SN)
{
    int idx = blockIdx.x * 8 + (threadIdx.x >> 5);
    if (idx >= SN) return;
    int lane = threadIdx.x & 31;
    int s = idx / NH;
    int n = idx - s * NH;
    const float* qr = q + (size_t)s * DIM + n * HD;
    const float* gm = gkm + n * HD;
    float acc = 0.f;
#pragma unroll
    for (int d = lane; d < HD; d += 32) acc += fmaxf(qr[d], 0.f) * gm[d];
#pragma unroll
    for (int o = 16; o; o >>= 1) acc += __shfl_xor_sync(0xffffffffu, acc, o);
    if (lane == 0) z[idx] = 1.f / (acc + 1e-6f);
}

// ---------------- RoPE in place (c=64 pairs: [0,22) frame, [22,43) h, [43,64) w) -------
__global__ void rope_kernel(
    float* __restrict__ q, float* __restrict__ k,
    const float* __restrict__ freqs,
    const int* __restrict__ ph, const int* __restrict__ pw, int S)
{
    int s = blockIdx.x;
    int n = blockIdx.y;
    float* buf = (blockIdx.z == 0 ? q : k) + (size_t)s * DIM + n * HD;
    int hg = *ph;
    int wg = *pw;
    int hw = hg * wg;
    int f = s / hw;
    int rem = s - f * hw;
    int hh = rem / wg;
    int ww = rem - hh * wg;
    int j = threadIdx.x;                 // pair index 0..63
    int pos = (j < 22) ? f : ((j < 43) ? hh : ww);
    float cr = freqs[(pos * 64 + j) * 2 + 0];
    float ci = freqs[(pos * 64 + j) * 2 + 1];
    float xr = buf[2 * j];
    float xi = buf[2 * j + 1];
    buf[2 * j]     = xr * cr - xi * ci;
    buf[2 * j + 1] = xr * ci + xi * cr;
}

// ---------------- G[n][d][j] = sum_m g_kv[n][d][m] * Wlin[j][m] ----------------
__global__ void __launch_bounds__(256) gmat_kernel(
    const float* __restrict__ gkv, const float* __restrict__ Wlin,
    float* __restrict__ G)
{
    int n = blockIdx.x;
    int jb = blockIdx.y * 64;
    __shared__ float Wl[64][128];
    int tid = threadIdx.x;
    for (int i = tid; i < 64 * 128; i += 256)
        Wl[i >> 7][i & 127] = Wlin[(jb + (i >> 7)) * HD + (i & 127)];
    __syncthreads();
    for (int o = tid; o < 128 * 64; o += 256) {
        int d = o >> 6;
        int jl = o & 63;
        const float* gr = gkv + ((size_t)n * HD + d) * HD;
        float acc = 0.f;
#pragma unroll 8
        for (int m = 0; m < HD; m++) acc += gr[m] * Wl[jl][m];
        G[((size_t)n * HD + d) * HD + jb + jl] = acc;
    }
}

// ---------------- 3xTF32 mma flash attention, 64(q) x 32(k) tiles ----------------
// smem (floats): Qhi 64*132, Qlo 64*132, Khi 32*132, Klo 32*132,
//                Vhi 32*136, Vlo 32*136, Ps 64*36 (scores, then P_hi), Plo 64*36,
//                rmx 64, rls 64, ral 64
#define ATTN_SMEM_FLOATS (64*132*2 + 32*132*2 + 32*136*2 + 64*36*2 + 192)

__global__ void __launch_bounds__(256) attn_mma_kernel(
    const float* __restrict__ rq, const float* __restrict__ rk,
    const float* __restrict__ v, float* __restrict__ xl, int S)
{
    extern __shared__ float sm[];
    float* Qhi = sm;
    float* Qlo = Qhi + 64 * 132;
    float* Khi = Qlo + 64 * 132;
    float* Klo = Khi + 32 * 132;
    float* Vhi = Klo + 32 * 132;
    float* Vlo = Vhi + 32 * 136;
    float* Ps  = Vlo + 32 * 136;
    float* Plo = Ps  + 64 * 36;
    float* rmx = Plo + 64 * 36;
    float* rls = rmx + 64;
    float* ral = rls + 64;

    const int head = blockIdx.y;
    const int q0 = blockIdx.x * 64;
    const int tid = threadIdx.x;
    const int w = tid >> 5;
    const int lane = tid & 31;
    const int r4 = lane >> 2;   // 0..7
    const int c4 = lane & 3;    // 0..3
    const float scale = 0.08838834764831843f; // 128^-0.5 (folded into Q)

    // ---- load Q tile (scaled), split hi/lo ----
    for (int i = tid; i < 64 * 32; i += 256) {
        int r = i >> 5, c = (i & 31) << 2;
        int s = q0 + r;
        float4 val = make_float4(0.f, 0.f, 0.f, 0.f);
        if (s < S) val = *(const float4*)(rq + (size_t)s * DIM + head * HD + c);
        val.x *= scale; val.y *= scale; val.z *= scale; val.w *= scale;
        float4 hi, lo;
        hi.x = tf32r(val.x); lo.x = tf32r(val.x - hi.x);
        hi.y = tf32r(val.y); lo.y = tf32r(val.y - hi.y);
        hi.z = tf32r(val.z); lo.z = tf32r(val.z - hi.z);
        hi.w = tf32r(val.w); lo.w = tf32r(val.w - hi.w);
        *(float4*)(Qhi + r * 132 + c) = hi;
        *(float4*)(Qlo + r * 132 + c) = lo;
    }
    if (tid < 64) { rmx[tid] = -1e30f; rls[tid] = 0.f; }

    float oacc[8][4];
#pragma unroll
    for (int i = 0; i < 8; i++)
#pragma unroll
        for (int j = 0; j < 4; j++) oacc[i][j] = 0.f;
    __syncthreads();

    const int rb = (w >> 1) * 16;   // QK & PV row base for this warp
    const int cb = (w & 1) * 16;    // QK col base
    const int nb = (w & 1) * 64;    // PV out-col base

    const float* qhp = Qhi + (rb + r4) * 132 + c4;
    const float* qlp = Qlo + (rb + r4) * 132 + c4;
    const float* php = Ps  + (rb + r4) * 36 + c4;
    const float* plp = Plo + (rb + r4) * 36 + c4;

    const int nkt = (S + 31) >> 5;
    for (int kt = 0; kt < nkt; kt++) {
        const int k0g = kt * 32;
        // ---- load K,V tiles, split hi/lo ----
        for (int i = tid; i < 32 * 32; i += 256) {
            int r = i >> 5, c = (i & 31) << 2;
            int t = k0g + r;
            float4 kv = make_float4(0.f, 0.f, 0.f, 0.f);
            float4 vv = make_float4(0.f, 0.f, 0.f, 0.f);
            if (t < S) {
                kv = *(const float4*)(rk + (size_t)t * DIM + head * HD + c);
                vv = *(const float4*)(v  + (size_t)t * DIM + head * HD + c);
            }
            float4 hi, lo;
            hi.x = tf32r(kv.x); lo.x = tf32r(kv.x - hi.x);
            hi.y = tf32r(kv.y); lo.y = tf32r(kv.y - hi.y);
            hi.z = tf32r(kv.z); lo.z = tf32r(kv.z - hi.z);
            hi.w = tf32r(kv.w); lo.w = tf32r(kv.w - hi.w);
            *(float4*)(Khi + r * 132 + c) = hi;
            *(float4*)(Klo + r * 132 + c) = lo;
            hi.x = tf32r(vv.x); lo.x = tf32r(vv.x - hi.x);
            hi.y = tf32r(vv.y); lo.y = tf32r(vv.y - hi.y);
            hi.z = tf32r(vv.z); lo.z = tf32r(vv.z - hi.z);
            hi.w = tf32r(vv.w); lo.w = tf32r(vv.w - hi.w);
            *(float4*)(Vhi + r * 136 + c) = hi;
            *(float4*)(Vlo + r * 136 + c) = lo;
        }
        __syncthreads();

        // ---- QK^T: 3xTF32, warp tile 16x16 ----
        float sacc[2][4];
#pragma unroll
        for (int i = 0; i < 2; i++)
#pragma unroll
            for (int j = 0; j < 4; j++) sacc[i][j] = 0.f;

        const float* kh0 = Khi + (cb + r4) * 132 + c4;
        const float* kl0 = Klo + (cb + r4) * 132 + c4;
        const float* kh1 = Khi + (cb + 8 + r4) * 132 + c4;
        const float* kl1 = Klo + (cb + 8 + r4) * 132 + c4;
#pragma unroll
        for (int ks = 0; ks < 16; ks++) {
            const int k0 = ks * 8;
            float ah0 = qhp[k0], ah1 = qhp[k0 + 8 * 132], ah2 = qhp[k0 + 4], ah3 = qhp[k0 + 8 * 132 + 4];
            float al0 = qlp[k0], al1 = qlp[k0 + 8 * 132], al2 = qlp[k0 + 4], al3 = qlp[k0 + 8 * 132 + 4];
            {
                float bh0 = kh0[k0], bh1 = kh0[k0 + 4];
                float bl0 = kl0[k0], bl1 = kl0[k0 + 4];
                mma8(sacc[0], ah0, ah1, ah2, ah3, bh0, bh1);
                mma8(sacc[0], ah0, ah1, ah2, ah3, bl0, bl1);
                mma8(sacc[0], al0, al1, al2, al3, bh0, bh1);
            }
            {
                float bh0 = kh1[k0], bh1 = kh1[k0 + 4];
                float bl0 = kl1[k0], bl1 = kl1[k0 + 4];
                mma8(sacc[1], ah0, ah1, ah2, ah3, bh0, bh1);
                mma8(sacc[1], ah0, ah1, ah2, ah3, bl0, bl1);
                mma8(sacc[1], al0, al1, al2, al3, bh0, bh1);
            }
        }
        // write scores
        {
            int srow = rb + r4;
#pragma unroll
            for (int nt = 0; nt < 2; nt++) {
                int scol = cb + nt * 8 + c4 * 2;
                Ps[srow * 36 + scol]           = sacc[nt][0];
                Ps[srow * 36 + scol + 1]       = sacc[nt][1];
                Ps[(srow + 8) * 36 + scol]     = sacc[nt][2];
                Ps[(srow + 8) * 36 + scol + 1] = sacc[nt][3];
            }
        }
        __syncthreads();

        // ---- online softmax, one thread per row; writes P hi/lo ----
        if (tid < 64) {
            int valid = S - k0g; if (valid > 32) valid = 32;
            float mold = rmx[tid];
            float mx = mold;
            float* srow = Ps + tid * 36;
            for (int c = 0; c < valid; c++) mx = fmaxf(mx, srow[c]);
            float a = __expf(mold - mx);
            float sum = 0.f;
            float* lrow = Plo + tid * 36;
#pragma unroll 8
            for (int c = 0; c < 32; c++) {
                float p = (c < valid) ? __expf(srow[c] - mx) : 0.f;
                float phv = tf32r(p);
                srow[c] = phv;
                lrow[c] = tf32r(p - phv);
                sum += p;
            }
            rls[tid] = rls[tid] * a + sum;
            rmx[tid] = mx;
            ral[tid] = a;
        }
        __syncthreads();

        // ---- rescale + PV (3xTF32), warp tile 16x64 ----
        {
            float a1v = ral[rb + r4];
            float a2v = ral[rb + 8 + r4];
#pragma unroll
            for (int nt = 0; nt < 8; nt++) {
                oacc[nt][0] *= a1v; oacc[nt][1] *= a1v;
                oacc[nt][2] *= a2v; oacc[nt][3] *= a2v;
            }
        }
#pragma unroll
        for (int ks = 0; ks < 4; ks++) {
            const int k0 = ks * 8;
            float ah0 = php[k0], ah1 = php[k0 + 8 * 36], ah2 = php[k0 + 4], ah3 = php[k0 + 8 * 36 + 4];
            float al0 = plp[k0], al1 = plp[k0 + 8 * 36], al2 = plp[k0 + 4], al3 = plp[k0 + 8 * 36 + 4];
            const float* vh = Vhi + (k0 + c4) * 136 + nb + r4;
            const float* vl = Vlo + (k0 + c4) * 136 + nb + r4;
#pragma unroll
            for (int nt = 0; nt < 8; nt++) {
                float bh0 = vh[nt * 8], bh1 = vh[nt * 8 + 4 * 136];
                float bl0 = vl[nt * 8], bl1 = vl[nt * 8 + 4 * 136];
                mma8(oacc[nt], ah0, ah1, ah2, ah3, bh0, bh1);
                mma8(oacc[nt], ah0, ah1, ah2, ah3, bl0, bl1);
                mma8(oacc[nt], al0, al1, al2, al3, bh0, bh1);
            }
        }
        __syncthreads();
    }

    // ---- epilogue ----
    {
        float inv1 = 1.f / rls[rb + r4];
        float inv2 = 1.f / rls[rb + 8 + r4];
        int s1 = q0 + rb + r4;
        int s2 = s1 + 8;
#pragma unroll
        for (int nt = 0; nt < 8; nt++) {
            int col = head * HD + nb + nt * 8 + c4 * 2;
            if (s1 < S) {
                float2 o = make_float2(oacc[nt][0] * inv1, oacc[nt][1] * inv1);
                *(float2*)(xl + (size_t)s1 * DIM + col) = o;
            }
            if (s2 < S) {
                float2 o = make_float2(oacc[nt][2] * inv2, oacc[nt][3] * inv2);
                *(float2*)(xl + (size_t)s2 * DIM + col) = o;
            }
        }
    }
}

// ---------------- gating: xl[s, n*128+j] += z[s,n] * (rq . G[n][:][j]) + blin[j] --------
__global__ void __launch_bounds__(256) gate_kernel(
    const float* __restrict__ rq, const float* __restrict__ G,
    const float* __restrict__ z, const float* __restrict__ blin,
    float* __restrict__ xl, int S)
{
    __shared__ float Qs[32][128];
    int n = blockIdx.y;
    int s0 = blockIdx.x * 32;
    int tid = threadIdx.x;
    for (int i = tid; i < 32 * 32; i += 256) {
        int r = i >> 5, c = (i & 31) << 2;
        int s = s0 + r;
        float4 val = make_float4(0.f, 0.f, 0.f, 0.f);
        if (s < S) val = *(const float4*)(rq + (size_t)s * DIM + n * HD + c);
        *(float4*)(&Qs[r][c]) = val;
    }
    __syncthreads();
    int j = tid & 127;
    int half = tid >> 7;   // two 16-row groups
    float acc[16];
#pragma unroll
    for (int r = 0; r < 16; r++) acc[r] = 0.f;
    const float* gp = G + (size_t)n * HD * HD + j;  // stride HD over d, coalesced over j
#pragma unroll 4
    for (int d = 0; d < 128; d++) {
        float gg = gp[d * HD];
#pragma unroll
        for (int r = 0; r < 16; r++) acc[r] += Qs[half * 16 + r][d] * gg;
    }
    float bl = blin[j];
#pragma unroll
    for (int r = 0; r < 16; r++) {
        int s = s0 + half * 16 + r;
        if (s < S) {
            float zz = z[s * NH + n];
            xl[(size_t)s * DIM + n * HD + j] += zz * acc[r] + bl;
        }
    }
}

// ---------------- launch ----------------
extern "C" void kernel_launch(void* const* d_in, const int* in_sizes, int n_in,
                              void* d_out, int out_size)
{
    const float* x    = (const float*)d_in[0];
    const float* freqs= (const float*)d_in[1];
    const float* gkm  = (const float*)d_in[2];
    const float* gkv  = (const float*)d_in[3];
    const float* Wq   = (const float*)d_in[4];
    const float* bq   = (const float*)d_in[5];
    const float* Wk   = (const float*)d_in[6];
    const float* bk   = (const float*)d_in[7];
    const float* Wv   = (const float*)d_in[8];
    const float* bv   = (const float*)d_in[9];
    const float* Wo   = (const float*)d_in[10];
    const float* bo   = (const float*)d_in[11];
    const float* gq   = (const float*)d_in[12];
    const float* gk   = (const float*)d_in[13];
    const float* Wlin = (const float*)d_in[14];
    const float* blin = (const float*)d_in[15];
    const int*   ph   = (const int*)d_in[17];
    const int*   pw   = (const int*)d_in[18];
    float* out = (float*)d_out;

    const int S = in_sizes[0] / DIM;

    float *bufq, *bufk, *bufv, *bufxl, *zb, *Gb;
    cudaGetSymbolAddress((void**)&bufq,  g_bufq);
    cudaGetSymbolAddress((void**)&bufk,  g_bufk);
    cudaGetSymbolAddress((void**)&bufv,  g_bufv);
    cudaGetSymbolAddress((void**)&bufxl, g_bufxl);
    cudaGetSymbolAddress((void**)&zb,    g_zbuf);
    cudaGetSymbolAddress((void**)&Gb,    g_Gmat);

    const int mt = (S + 127) / 128;

    // 1. q/k/v projections (fused launch)
    gemm_qkv<<<dim3(DIM / 128, mt, 3), 256>>>(x, Wq, bq, Wk, bk, Wv, bv,
                                              bufq, bufk, bufv, S);
    // 2. rms norm (in place) on q and k
    rms_kernel<<<dim3(S, 2), 256>>>(bufq, bufk, gq, gk, S);
    // 3. z from post-rms pre-rope q
    z_kernel<<<(S * NH + 7) / 8, 256>>>(bufq, gkm, zb, S * NH);
    // 4. rope in place on q and k
    rope_kernel<<<dim3(S, NH, 2), 64>>>(bufq, bufk, freqs, ph, pw, S);
    // 5. G[n] = g_kv[n] @ Wlin^T
    gmat_kernel<<<dim3(NH, 2), 256>>>(gkv, Wlin, Gb);
    // 6. attention -> bufxl (3xTF32 tensor-core flash attention)
    const int attn_smem = ATTN_SMEM_FLOATS * 4;
    cudaFuncSetAttribute(attn_mma_kernel, cudaFuncAttributeMaxDynamicSharedMemorySize, attn_smem);
    attn_mma_kernel<<<dim3((S + 63) / 64, NH), 256, attn_smem>>>(bufq, bufk, bufv, bufxl, S);
    // 7. gating += into bufxl
    gate_kernel<<<dim3((S + 31) / 32, NH), 256>>>(bufq, Gb, zb, blin, bufxl, S);
    // 8. output projection
    gemm_nt_bias<<<dim3(DIM / 128, mt), 256>>>(bufxl, Wo, bo, out, S, DIM, DIM);
}